// round 14
// baseline (speedup 1.0000x reference)
#include <cuda_runtime.h>

// Masked inclusive cumsum along rows.
//   x:    [2048, 32768] fp32
//   mask: [2048, 32768] bool, serialized by the harness as INT32 (0/1)
//   out:  [2048, 32768] fp32, out[r, j] = sum_{i<=j} (mask[r,i] ? x[r,i] : 0)
//
// One CTA per row. 1024 threads, 8 sequential tiles of 4096 elements
// (float4 + int4 per thread per tile). Two-level block scan per tile
// (warp shuffle scan + 32-entry smem warp-total scan), carry register
// across tiles. Traffic: 256 MB x + 256 MB mask + 256 MB out = 768 MB
// -> ~112 us floor at ~6.8 TB/s.

#define NCOLS    32768
#define THREADS  1024
#define NTILES   (NCOLS / (THREADS * 4))   // 8

__global__ void __launch_bounds__(THREADS, 2)
masked_cumsum_kernel(const float4* __restrict__ x,
                     const int4*   __restrict__ mask,
                     float4*       __restrict__ out)
{
    __shared__ float warp_sums[32];

    const int tid  = threadIdx.x;
    const int lane = tid & 31;
    const int wid  = tid >> 5;

    const size_t row4 = (size_t)blockIdx.x * (NCOLS / 4);
    const float4* __restrict__ xr   = x    + row4;
    const int4*   __restrict__ mr   = mask + row4;
    float4*       __restrict__ orow = out  + row4;

    float carry = 0.0f;

    #pragma unroll
    for (int t = 0; t < NTILES; ++t) {
        const int idx = t * THREADS + tid;

        // Coalesced vector loads: 16B x + 16B mask per thread.
        float4 v = xr[idx];
        int4   m = mr[idx];

        // Apply mask, thread-local inclusive prefix over 4 elements.
        float a0 = m.x ? v.x : 0.0f;
        float a1 = m.y ? v.y : 0.0f;
        float a2 = m.z ? v.z : 0.0f;
        float a3 = m.w ? v.w : 0.0f;
        float s1 = a0;
        float s2 = s1 + a1;
        float s3 = s2 + a2;
        float s4 = s3 + a3;

        // Warp-level inclusive scan of per-thread sums.
        float incl = s4;
        #pragma unroll
        for (int d = 1; d < 32; d <<= 1) {
            float n = __shfl_up_sync(0xffffffffu, incl, d);
            if (lane >= d) incl += n;
        }

        // Protect warp_sums from the previous tile's readers before rewrite.
        if (t > 0) __syncthreads();
        if (lane == 31) warp_sums[wid] = incl;
        __syncthreads();

        // Warp 0 scans the 32 warp totals in place (inclusive).
        if (wid == 0) {
            float ws = warp_sums[lane];
            #pragma unroll
            for (int d = 1; d < 32; d <<= 1) {
                float n = __shfl_up_sync(0xffffffffu, ws, d);
                if (lane >= d) ws += n;
            }
            warp_sums[lane] = ws;
        }
        __syncthreads();

        // base = everything strictly before this thread's first element.
        const float warp_off = (wid > 0) ? warp_sums[wid - 1] : 0.0f;
        const float base = carry + warp_off + (incl - s4);
        carry += warp_sums[31];   // block total -> carry into next tile

        float4 o;
        o.x = base + s1;
        o.y = base + s2;
        o.z = base + s3;
        o.w = base + s4;
        orow[idx] = o;
    }
}

extern "C" void kernel_launch(void* const* d_in, const int* in_sizes, int n_in,
                              void* d_out, int out_size)
{
    const float4* x    = (const float4*)d_in[0];
    const int4*   mask = (const int4*)d_in[1];
    float4*       out  = (float4*)d_out;

    const int rows = in_sizes[0] / NCOLS;   // 2048

    masked_cumsum_kernel<<<rows, THREADS>>>(x, mask, out);
}